// round 16
// baseline (speedup 1.0000x reference)
#include <cuda_runtime.h>
#include <cuda_fp16.h>
#include <cstdint>
#include <cstddef>

#define NE_ 8
#define DIM 2048
#define HIDDEN 7168
#define NTOK 2048

// ---------------- device scratch ----------------
__device__ int    g_cnt[NE_];
__device__ int    g_tok[NE_][NTOK];
__device__ int    g_slotA[NE_][NTOK];
__device__ float  g_wt[NE_][NTOK];
__device__ __half g_w1h[(size_t)NE_ * DIM * HIDDEN];
__device__ __half g_w3h[(size_t)NE_ * DIM * HIDDEN];
__device__ __half g_w2h[(size_t)NE_ * HIDDEN * DIM];
__device__ __half g_xh[(size_t)NTOK * DIM];
__device__ __half g_hh[(size_t)NTOK * 2 * HIDDEN];

// ---------------- helpers ----------------
__device__ __forceinline__ uint32_t smem_u32(const void* p) {
    uint32_t a;
    asm("{ .reg .u64 t; cvta.to.shared.u64 t, %1; cvt.u32.u64 %0, t; }" : "=r"(a) : "l"(p));
    return a;
}
__device__ __forceinline__ void ldsm4(unsigned* r, uint32_t a) {
    asm volatile("ldmatrix.sync.aligned.m8n8.x4.shared.b16 {%0,%1,%2,%3}, [%4];"
                 : "=r"(r[0]), "=r"(r[1]), "=r"(r[2]), "=r"(r[3]) : "r"(a));
}
__device__ __forceinline__ void ldsm4t(unsigned* r, uint32_t a) {
    asm volatile("ldmatrix.sync.aligned.m8n8.x4.trans.shared.b16 {%0,%1,%2,%3}, [%4];"
                 : "=r"(r[0]), "=r"(r[1]), "=r"(r[2]), "=r"(r[3]) : "r"(a));
}
__device__ __forceinline__ void mma16(float* c, const unsigned* a, unsigned b0, unsigned b1) {
    asm("mma.sync.aligned.m16n8k16.row.col.f32.f16.f16.f32 "
        "{%0,%1,%2,%3}, {%4,%5,%6,%7}, {%8,%9}, {%0,%1,%2,%3};"
        : "+f"(c[0]), "+f"(c[1]), "+f"(c[2]), "+f"(c[3])
        : "r"(a[0]), "r"(a[1]), "r"(a[2]), "r"(a[3]), "r"(b0), "r"(b1));
}
__device__ __forceinline__ void cvt8_to(__half* dst, const float* src) {
    float4 v0 = *(const float4*)(src);
    float4 v1 = *(const float4*)(src + 4);
    __half2 h0 = __floats2half2_rn(v0.x, v0.y);
    __half2 h1 = __floats2half2_rn(v0.z, v0.w);
    __half2 h2 = __floats2half2_rn(v1.x, v1.y);
    __half2 h3 = __floats2half2_rn(v1.z, v1.w);
    *(uint4*)dst = make_uint4(*(unsigned*)&h0, *(unsigned*)&h1,
                              *(unsigned*)&h2, *(unsigned*)&h3);
}
#define CPA(dst, src) asm volatile("cp.async.cg.shared.global [%0], [%1], 16;" :: "r"(dst), "l"(src) : "memory")
#define CPC() asm volatile("cp.async.commit_group;" ::: "memory")
#define CPW1() asm volatile("cp.async.wait_group 1;" ::: "memory")
#define CPW0() asm volatile("cp.async.wait_group 0;" ::: "memory")

// ---------------- kernel 0: reset counters + zero out (must precede gate) ----
__global__ void zero_kernel(float* __restrict__ out, int n) {
    int idx = blockIdx.x * blockDim.x + threadIdx.x;
    if (idx < NE_) g_cnt[idx] = 0;
    for (int i = idx; i < n; i += gridDim.x * blockDim.x) out[i] = 0.f;
}

// ---------------- prep: cvt w1/w3 + cvt x + gate, one launch, block sections -
__global__ void prep_kernel(const float* __restrict__ x, const float* __restrict__ Wg,
                            const float* __restrict__ w1, const float* __restrict__ w3) {
    int bx = blockIdx.x;
    if (bx < 2048) {
        // ---- w1/w3 f32 -> f16 (1024 blocks each) ----
        const float* src = (bx < 1024) ? w1 : w3;
        __half* dst = (bx < 1024) ? g_w1h : g_w3h;
        int b = bx & 1023;
        const size_t N = (size_t)NE_ * DIM * HIDDEN;
        size_t i = ((size_t)b * blockDim.x + threadIdx.x) * 8;
        size_t stride = (size_t)1024 * blockDim.x * 8;
        for (; i < N; i += stride) cvt8_to(dst + i, src + i);
    } else if (bx < 2304) {
        // ---- x f32 -> f16 (256 blocks) ----
        int b = bx - 2048;
        const size_t N = (size_t)NTOK * DIM;
        size_t i = ((size_t)b * blockDim.x + threadIdx.x) * 8;
        size_t stride = (size_t)256 * blockDim.x * 8;
        for (; i < N; i += stride) cvt8_to(g_xh + i, x + i);
    } else {
        // ---- gating (256 blocks x 8 warps = 2048 tokens) ----
        int lane = threadIdx.x & 31;
        int t = (bx - 2304) * 8 + (threadIdx.x >> 5);
        if (t >= NTOK) return;
        const float* xr = x + (size_t)t * DIM;
        float acc[NE_];
#pragma unroll
        for (int e = 0; e < NE_; e++) acc[e] = 0.f;
        for (int d = lane; d < DIM; d += 32) {
            float xv = xr[d];
            const float* wr = Wg + d * NE_;
#pragma unroll
            for (int e = 0; e < NE_; e++) acc[e] += xv * wr[e];
        }
#pragma unroll
        for (int e = 0; e < NE_; e++)
#pragma unroll
            for (int s = 16; s > 0; s >>= 1) acc[e] += __shfl_xor_sync(0xffffffffu, acc[e], s);
        if (lane == 0) {
            int b0 = 0;
#pragma unroll
            for (int e = 1; e < NE_; e++) if (acc[e] > acc[b0]) b0 = e;
            int b1 = (b0 == 0) ? 1 : 0;
#pragma unroll
            for (int e = 0; e < NE_; e++) if (e != b0 && acc[e] > acc[b1]) b1 = e;
            float d1 = expf(acc[b1] - acc[b0]);
            float inv = 1.f / (1.f + d1);
            int p0 = atomicAdd(&g_cnt[b0], 1);
            g_tok[b0][p0] = t; g_slotA[b0][p0] = 2 * t;     g_wt[b0][p0] = inv;
            int p1 = atomicAdd(&g_cnt[b1], 1);
            g_tok[b1][p1] = t; g_slotA[b1][p1] = 2 * t + 1; g_wt[b1][p1] = d1 * inv;
        }
    }
}

// ============================================================================
// GEMM1 (fp16): dual (x@w1, x@w3) + SwiGLU -> g_hh.
// BM=128, BN=64 (dual), BK=32, 512 threads, 3-stage cp.async.
// blockIdx.z == 8 : side-band w2 f32->f16 conversion (overlapped streaming).
// ============================================================================
#define S1 19456
#define KT1 (DIM / 32)

__global__ __launch_bounds__(512, 2)
void gemm1_k(const float* __restrict__ w2) {
    if (blockIdx.z == 8) {
        // ---- convert w2 under gemm1's compute shadow ----
        const size_t N = (size_t)NE_ * HIDDEN * DIM;
        int cid = blockIdx.y * gridDim.x + blockIdx.x;          // 0..1791
        size_t i = ((size_t)cid * blockDim.x + threadIdx.x) * 8;
        size_t stride = (size_t)1792 * blockDim.x * 8;
        for (; i < N; i += stride) cvt8_to(g_w2h + i, w2 + i);
        return;
    }

    int e = blockIdx.z, Ne = g_cnt[e];
    int m0 = blockIdx.x * 128;
    if (m0 >= Ne) return;
    int n0 = blockIdx.y * 64;

    extern __shared__ __align__(128) char sm[];
    uint32_t sb = smem_u32(sm);
    __shared__ int rtok[128], rslot[128];

    int tid = threadIdx.x, warp = tid >> 5, lane = tid & 31;
    if (tid < 128) {
        int r = m0 + tid;
        rtok[tid]  = (r < Ne) ? g_tok[e][r] : 0;
        rslot[tid] = (r < Ne) ? g_slotA[e][r] : -1;
    }
    __syncthreads();

    int am = tid >> 2, aq = tid & 3;
    const __half* asrc = g_xh + (size_t)rtok[am] * DIM + aq * 8;
    uint32_t adst = sb + am * 80 + aq * 16;
    int bmat = tid >> 8, bt = tid & 255;
    int br = bt >> 3, bq = bt & 7;
    const __half* bsrc = (bmat ? g_w3h : g_w1h) + (size_t)e * DIM * HIDDEN + n0
                         + (size_t)br * HIDDEN + bq * 8;
    uint32_t bdst = sb + 10240 + bmat * 4608 + br * 144 + bq * 16;

    auto fill = [&](int s, int k0) {
        uint32_t so = (uint32_t)s * S1;
        CPA(adst + so, asrc + k0);
        CPA(bdst + so, bsrc + (size_t)k0 * HIDDEN);
    };

    int m_base = (warp >> 2) * 32, n_base = (warp & 3) * 16;
    int lrow = (lane & 7) + ((lane >> 3) & 1) * 8;
    uint32_t abase = sb + (m_base + lrow) * 80 + (lane >> 4) * 16;
    uint32_t bbase = sb + 10240 + lrow * 144 + (lane >> 4) * 16 + n_base * 2;

    float acc1[2][2][4], acc3[2][2][4];
#pragma unroll
    for (int a = 0; a < 2; a++)
#pragma unroll
        for (int b = 0; b < 2; b++)
#pragma unroll
            for (int c = 0; c < 4; c++) { acc1[a][b][c] = 0.f; acc3[a][b][c] = 0.f; }

    fill(0, 0);  CPC();
    fill(1, 32); CPC();
    CPW1(); __syncthreads();

    int s = 0, fs = 2;
    for (int kt = 0; kt < KT1; kt++) {
        uint32_t so = (uint32_t)s * S1;
#pragma unroll
        for (int ks = 0; ks < 2; ks++) {
            unsigned a[2][4];
            ldsm4(a[0], abase + so + ks * 32);
            ldsm4(a[1], abase + so + 1280 + ks * 32);
            unsigned bf1[4], bf3[4];
            uint32_t bb = bbase + so + ks * 2304;
            ldsm4t(bf1, bb);
            ldsm4t(bf3, bb + 4608);
#pragma unroll
            for (int mt = 0; mt < 2; mt++) {
                mma16(acc1[mt][0], a[mt], bf1[0], bf1[1]);
                mma16(acc1[mt][1], a[mt], bf1[2], bf1[3]);
                mma16(acc3[mt][0], a[mt], bf3[0], bf3[1]);
                mma16(acc3[mt][1], a[mt], bf3[2], bf3[3]);
            }
        }
        int nk = kt + 2;
        if (nk < KT1) fill(fs, nk * 32);
        CPC();
        CPW1(); __syncthreads();
        s = (s == 2) ? 0 : s + 1;
        fs = (fs == 2) ? 0 : fs + 1;
    }
    CPW0();

#pragma unroll
    for (int mt = 0; mt < 2; mt++) {
        int mloc = m_base + mt * 16 + (lane >> 2);
        int s_lo = rslot[mloc], s_hi = rslot[mloc + 8];
#pragma unroll
        for (int nt = 0; nt < 2; nt++) {
            int col = n0 + n_base + nt * 8 + 2 * (lane & 3);
            if (s_lo >= 0) {
                __half2* hp = (__half2*)(g_hh + (size_t)s_lo * HIDDEN + col);
                float a0 = acc1[mt][nt][0], a1 = acc1[mt][nt][1];
                *hp = __floats2half2_rn(a0 / (1.f + __expf(-a0)) * acc3[mt][nt][0],
                                        a1 / (1.f + __expf(-a1)) * acc3[mt][nt][1]);
            }
            if (s_hi >= 0) {
                __half2* hp = (__half2*)(g_hh + (size_t)s_hi * HIDDEN + col);
                float a2 = acc1[mt][nt][2], a3 = acc1[mt][nt][3];
                *hp = __floats2half2_rn(a2 / (1.f + __expf(-a2)) * acc3[mt][nt][2],
                                        a3 / (1.f + __expf(-a3)) * acc3[mt][nt][3]);
            }
        }
    }
}

// ============================================================================
// GEMM2 (fp16): out += wt * (h @ w2). BM=128, BN=128, BK=32, 512 threads.
// ============================================================================
#define S2 18944
#define KT2 (HIDDEN / 32)

__global__ __launch_bounds__(512, 2)
void gemm2_k(float* __restrict__ out) {
    int e = blockIdx.z, Ne = g_cnt[e];
    int m0 = blockIdx.x * 128;
    if (m0 >= Ne) return;
    int n0 = blockIdx.y * 128;

    extern __shared__ __align__(128) char sm[];
    uint32_t sb = smem_u32(sm);
    __shared__ int rtok[128], rsl[128];
    __shared__ float rwt[128];

    int tid = threadIdx.x, warp = tid >> 5, lane = tid & 31;
    if (tid < 128) {
        int r = m0 + tid;
        if (r < Ne) { rtok[tid] = g_tok[e][r]; rsl[tid] = g_slotA[e][r]; rwt[tid] = g_wt[e][r]; }
        else        { rtok[tid] = -1; rsl[tid] = 0; rwt[tid] = 0.f; }
    }
    __syncthreads();

    int am = tid >> 2, aq = tid & 3;
    const __half* asrc = g_hh + (size_t)rsl[am] * HIDDEN + aq * 8;
    uint32_t adst = sb + am * 80 + aq * 16;
    int br = tid >> 4, bq = tid & 15;
    const __half* bsrc = g_w2h + (size_t)e * HIDDEN * DIM + n0 + (size_t)br * DIM + bq * 8;
    uint32_t bdst = sb + 10240 + br * 272 + bq * 16;

    auto fill = [&](int s, int k0) {
        uint32_t so = (uint32_t)s * S2;
        CPA(adst + so, asrc + k0);
        CPA(bdst + so, bsrc + (size_t)k0 * DIM);
    };

    int m_base = (warp >> 2) * 32, n_base = (warp & 3) * 32;
    int lrow = (lane & 7) + ((lane >> 3) & 1) * 8;
    uint32_t abase = sb + (m_base + lrow) * 80 + (lane >> 4) * 16;
    uint32_t bbase = sb + 10240 + lrow * 272 + (lane >> 4) * 16 + n_base * 2;

    float acc[2][4][4];
#pragma unroll
    for (int a = 0; a < 2; a++)
#pragma unroll
        for (int b = 0; b < 4; b++)
#pragma unroll
            for (int c = 0; c < 4; c++) acc[a][b][c] = 0.f;

    fill(0, 0);  CPC();
    fill(1, 32); CPC();
    CPW1(); __syncthreads();

    int s = 0, fs = 2;
    for (int kt = 0; kt < KT2; kt++) {
        uint32_t so = (uint32_t)s * S2;
#pragma unroll
        for (int ks = 0; ks < 2; ks++) {
            unsigned a[2][4];
            ldsm4(a[0], abase + so + ks * 32);
            ldsm4(a[1], abase + so + 1280 + ks * 32);
            unsigned bf[2][4];
            uint32_t bb = bbase + so + ks * 4352;
            ldsm4t(bf[0], bb);
            ldsm4t(bf[1], bb + 32);
#pragma unroll
            for (int mt = 0; mt < 2; mt++) {
#pragma unroll
                for (int h = 0; h < 2; h++) {
                    mma16(acc[mt][h * 2 + 0], a[mt], bf[h][0], bf[h][1]);
                    mma16(acc[mt][h * 2 + 1], a[mt], bf[h][2], bf[h][3]);
                }
            }
        }
        int nk = kt + 2;
        if (nk < KT2) fill(fs, nk * 32);
        CPC();
        CPW1(); __syncthreads();
        s = (s == 2) ? 0 : s + 1;
        fs = (fs == 2) ? 0 : fs + 1;
    }
    CPW0();

#pragma unroll
    for (int mt = 0; mt < 2; mt++) {
        int mloc = m_base + mt * 16 + (lane >> 2);
        int t_lo = rtok[mloc], t_hi = rtok[mloc + 8];
        float w_lo = rwt[mloc], w_hi = rwt[mloc + 8];
#pragma unroll
        for (int nt = 0; nt < 4; nt++) {
            int col = n0 + n_base + nt * 8 + 2 * (lane & 3);
            if (t_lo >= 0) {
                atomicAdd(&out[(size_t)t_lo * DIM + col],     w_lo * acc[mt][nt][0]);
                atomicAdd(&out[(size_t)t_lo * DIM + col + 1], w_lo * acc[mt][nt][1]);
            }
            if (t_hi >= 0) {
                atomicAdd(&out[(size_t)t_hi * DIM + col],     w_hi * acc[mt][nt][2]);
                atomicAdd(&out[(size_t)t_hi * DIM + col + 1], w_hi * acc[mt][nt][3]);
            }
        }
    }
}

// ---------------- launch ----------------
extern "C" void kernel_launch(void* const* d_in, const int* in_sizes, int n_in,
                              void* d_out, int out_size) {
    const float* x  = (const float*)d_in[0];
    const float* Wg = (const float*)d_in[1];
    const float* w1 = (const float*)d_in[2];
    const float* w3 = (const float*)d_in[3];
    const float* w2 = (const float*)d_in[4];
    float* out = (float*)d_out;

    cudaFuncSetAttribute(gemm1_k, cudaFuncAttributeMaxDynamicSharedMemorySize, 3 * S1);
    cudaFuncSetAttribute(gemm2_k, cudaFuncAttributeMaxDynamicSharedMemorySize, 3 * S2);

    zero_kernel<<<1024, 256>>>(out, out_size);          // g_cnt reset orders before gate
    prep_kernel<<<2560, 256>>>(x, Wg, w1, w3);          // cvt w1/w3 + cvt x + gate

    dim3 g1(NTOK / 128, HIDDEN / 64, NE_ + 1);          // z=8 slice converts w2 under shadow
    gemm1_k<<<g1, 512, 3 * S1>>>(w2);

    dim3 g2(NTOK / 128, DIM / 128, NE_);                // (16, 16, 8)
    gemm2_k<<<g2, 512, 3 * S2>>>(out);
}

// round 17
// speedup vs baseline: 1.4760x; 1.4760x over previous
#include <cuda_runtime.h>
#include <cuda_fp16.h>
#include <cstdint>
#include <cstddef>

#define NE_ 8
#define DIM 2048
#define HIDDEN 7168
#define NTOK 2048

// ---------------- device scratch ----------------
__device__ int    g_cnt[NE_];
__device__ int    g_cvt;                    // w2-conversion chunk ticket
__device__ int    g_tok[NE_][NTOK];
__device__ int    g_slotA[NE_][NTOK];
__device__ float  g_wt[NE_][NTOK];
__device__ __half g_w1h[(size_t)NE_ * DIM * HIDDEN];
__device__ __half g_w3h[(size_t)NE_ * DIM * HIDDEN];
__device__ __half g_w2h[(size_t)NE_ * HIDDEN * DIM];
__device__ __half g_xh[(size_t)NTOK * DIM];
__device__ __half g_hh[(size_t)NTOK * 2 * HIDDEN];

#define CVT_CHUNKS 8192
#define CVT_ELEMS  14336   // (8*2048*7168)/8192

// ---------------- helpers ----------------
__device__ __forceinline__ uint32_t smem_u32(const void* p) {
    uint32_t a;
    asm("{ .reg .u64 t; cvta.to.shared.u64 t, %1; cvt.u32.u64 %0, t; }" : "=r"(a) : "l"(p));
    return a;
}
__device__ __forceinline__ void ldsm4(unsigned* r, uint32_t a) {
    asm volatile("ldmatrix.sync.aligned.m8n8.x4.shared.b16 {%0,%1,%2,%3}, [%4];"
                 : "=r"(r[0]), "=r"(r[1]), "=r"(r[2]), "=r"(r[3]) : "r"(a));
}
__device__ __forceinline__ void ldsm4t(unsigned* r, uint32_t a) {
    asm volatile("ldmatrix.sync.aligned.m8n8.x4.trans.shared.b16 {%0,%1,%2,%3}, [%4];"
                 : "=r"(r[0]), "=r"(r[1]), "=r"(r[2]), "=r"(r[3]) : "r"(a));
}
__device__ __forceinline__ void mma16(float* c, const unsigned* a, unsigned b0, unsigned b1) {
    asm("mma.sync.aligned.m16n8k16.row.col.f32.f16.f16.f32 "
        "{%0,%1,%2,%3}, {%4,%5,%6,%7}, {%8,%9}, {%0,%1,%2,%3};"
        : "+f"(c[0]), "+f"(c[1]), "+f"(c[2]), "+f"(c[3])
        : "r"(a[0]), "r"(a[1]), "r"(a[2]), "r"(a[3]), "r"(b0), "r"(b1));
}
__device__ __forceinline__ void cvt8_to(__half* dst, const float* src) {
    float4 v0 = *(const float4*)(src);
    float4 v1 = *(const float4*)(src + 4);
    __half2 h0 = __floats2half2_rn(v0.x, v0.y);
    __half2 h1 = __floats2half2_rn(v0.z, v0.w);
    __half2 h2 = __floats2half2_rn(v1.x, v1.y);
    __half2 h3 = __floats2half2_rn(v1.z, v1.w);
    *(uint4*)dst = make_uint4(*(unsigned*)&h0, *(unsigned*)&h1,
                              *(unsigned*)&h2, *(unsigned*)&h3);
}
#define CPA(dst, src) asm volatile("cp.async.cg.shared.global [%0], [%1], 16;" :: "r"(dst), "l"(src) : "memory")
#define CPC() asm volatile("cp.async.commit_group;" ::: "memory")
#define CPW1() asm volatile("cp.async.wait_group 1;" ::: "memory")
#define CPW0() asm volatile("cp.async.wait_group 0;" ::: "memory")

// ---------------- kernel 0: reset counters + zero out ----------------
__global__ void zero_kernel(float* __restrict__ out, int n) {
    int idx = blockIdx.x * blockDim.x + threadIdx.x;
    if (idx < NE_) g_cnt[idx] = 0;
    if (idx == NE_) g_cvt = 0;
    for (int i = idx; i < n; i += gridDim.x * blockDim.x) out[i] = 0.f;
}

// ---------------- f32 -> f16 conversion: w1 and w3 only ----------------
__global__ void cvt_w_kernel(const float* __restrict__ w1, const float* __restrict__ w3) {
    const size_t N = (size_t)NE_ * DIM * HIDDEN;
    const float* src = (blockIdx.y == 0) ? w1 : w3;
    __half* dst = (blockIdx.y == 0) ? g_w1h : g_w3h;
    size_t i = (size_t)blockIdx.x * blockDim.x + threadIdx.x;
    size_t stride = (size_t)gridDim.x * blockDim.x;
    for (size_t j = i * 8; j < N; j += stride * 8) cvt8_to(dst + j, src + j);
}
__global__ void cvt_x_kernel(const float* __restrict__ x) {
    const size_t N = (size_t)NTOK * DIM;
    size_t i = (size_t)blockIdx.x * blockDim.x + threadIdx.x;
    size_t stride = (size_t)gridDim.x * blockDim.x;
    for (size_t j = i * 8; j < N; j += stride * 8) cvt8_to(g_xh + j, x + j);
}

// ---------------- kernel 1: gating (f32, verified) ----------------
__global__ void gate_kernel(const float* __restrict__ x, const float* __restrict__ Wg) {
    int lane = threadIdx.x & 31;
    int t = blockIdx.x * (blockDim.x >> 5) + (threadIdx.x >> 5);
    if (t >= NTOK) return;
    const float* xr = x + (size_t)t * DIM;
    float acc[NE_];
#pragma unroll
    for (int e = 0; e < NE_; e++) acc[e] = 0.f;
    for (int d = lane; d < DIM; d += 32) {
        float xv = xr[d];
        const float* wr = Wg + d * NE_;
#pragma unroll
        for (int e = 0; e < NE_; e++) acc[e] += xv * wr[e];
    }
#pragma unroll
    for (int e = 0; e < NE_; e++)
#pragma unroll
        for (int s = 16; s > 0; s >>= 1) acc[e] += __shfl_xor_sync(0xffffffffu, acc[e], s);
    if (lane == 0) {
        int b0 = 0;
#pragma unroll
        for (int e = 1; e < NE_; e++) if (acc[e] > acc[b0]) b0 = e;
        int b1 = (b0 == 0) ? 1 : 0;
#pragma unroll
        for (int e = 0; e < NE_; e++) if (e != b0 && acc[e] > acc[b1]) b1 = e;
        float d1 = expf(acc[b1] - acc[b0]);
        float inv = 1.f / (1.f + d1);
        int p0 = atomicAdd(&g_cnt[b0], 1);
        g_tok[b0][p0] = t; g_slotA[b0][p0] = 2 * t;     g_wt[b0][p0] = inv;
        int p1 = atomicAdd(&g_cnt[b1], 1);
        g_tok[b1][p1] = t; g_slotA[b1][p1] = 2 * t + 1; g_wt[b1][p1] = d1 * inv;
    }
}

// ============================================================================
// GEMM1 (fp16): dual (x@w1, x@w3) + SwiGLU -> g_hh.
// BM=128, BN=64 (dual), BK=32, 512 threads, 3-stage cp.async.
// Exiting blocks (m0 >= Ne) each convert ONE w2 chunk, then exit (bounded).
// ============================================================================
#define S1 19456
#define KT1 (DIM / 32)

__global__ __launch_bounds__(512, 2)
void gemm1_k(const float* __restrict__ w2) {
    int e = blockIdx.z, Ne = g_cnt[e];
    int m0 = blockIdx.x * 128;
    if (m0 >= Ne) {
        // one bounded w2-conversion chunk per exiting block
        __shared__ int tkt;
        if (threadIdx.x == 0) tkt = atomicAdd(&g_cvt, 1);
        __syncthreads();
        if (tkt < CVT_CHUNKS) {
            size_t base = (size_t)tkt * CVT_ELEMS;
            for (int j = threadIdx.x * 8; j < CVT_ELEMS; j += 512 * 8)
                cvt8_to(g_w2h + base + j, w2 + base + j);
        }
        return;
    }
    int n0 = blockIdx.y * 64;

    extern __shared__ __align__(128) char sm[];
    uint32_t sb = smem_u32(sm);
    __shared__ int rtok[128], rslot[128];

    int tid = threadIdx.x, warp = tid >> 5, lane = tid & 31;
    if (tid < 128) {
        int r = m0 + tid;
        rtok[tid]  = (r < Ne) ? g_tok[e][r] : 0;
        rslot[tid] = (r < Ne) ? g_slotA[e][r] : -1;
    }
    __syncthreads();

    int am = tid >> 2, aq = tid & 3;
    const __half* asrc = g_xh + (size_t)rtok[am] * DIM + aq * 8;
    uint32_t adst = sb + am * 80 + aq * 16;
    int bmat = tid >> 8, bt = tid & 255;
    int br = bt >> 3, bq = bt & 7;
    const __half* bsrc = (bmat ? g_w3h : g_w1h) + (size_t)e * DIM * HIDDEN + n0
                         + (size_t)br * HIDDEN + bq * 8;
    uint32_t bdst = sb + 10240 + bmat * 4608 + br * 144 + bq * 16;

    auto fill = [&](int s, int k0) {
        uint32_t so = (uint32_t)s * S1;
        CPA(adst + so, asrc + k0);
        CPA(bdst + so, bsrc + (size_t)k0 * HIDDEN);
    };

    int m_base = (warp >> 2) * 32, n_base = (warp & 3) * 16;
    int lrow = (lane & 7) + ((lane >> 3) & 1) * 8;
    uint32_t abase = sb + (m_base + lrow) * 80 + (lane >> 4) * 16;
    uint32_t bbase = sb + 10240 + lrow * 144 + (lane >> 4) * 16 + n_base * 2;

    float acc1[2][2][4], acc3[2][2][4];
#pragma unroll
    for (int a = 0; a < 2; a++)
#pragma unroll
        for (int b = 0; b < 2; b++)
#pragma unroll
            for (int c = 0; c < 4; c++) { acc1[a][b][c] = 0.f; acc3[a][b][c] = 0.f; }

    fill(0, 0);  CPC();
    fill(1, 32); CPC();
    CPW1(); __syncthreads();

    int s = 0, fs = 2;
    for (int kt = 0; kt < KT1; kt++) {
        uint32_t so = (uint32_t)s * S1;
#pragma unroll
        for (int ks = 0; ks < 2; ks++) {
            unsigned a[2][4];
            ldsm4(a[0], abase + so + ks * 32);
            ldsm4(a[1], abase + so + 1280 + ks * 32);
            unsigned bf1[4], bf3[4];
            uint32_t bb = bbase + so + ks * 2304;
            ldsm4t(bf1, bb);
            ldsm4t(bf3, bb + 4608);
#pragma unroll
            for (int mt = 0; mt < 2; mt++) {
                mma16(acc1[mt][0], a[mt], bf1[0], bf1[1]);
                mma16(acc1[mt][1], a[mt], bf1[2], bf1[3]);
                mma16(acc3[mt][0], a[mt], bf3[0], bf3[1]);
                mma16(acc3[mt][1], a[mt], bf3[2], bf3[3]);
            }
        }
        int nk = kt + 2;
        if (nk < KT1) fill(fs, nk * 32);
        CPC();
        CPW1(); __syncthreads();
        s = (s == 2) ? 0 : s + 1;
        fs = (fs == 2) ? 0 : fs + 1;
    }
    CPW0();

#pragma unroll
    for (int mt = 0; mt < 2; mt++) {
        int mloc = m_base + mt * 16 + (lane >> 2);
        int s_lo = rslot[mloc], s_hi = rslot[mloc + 8];
#pragma unroll
        for (int nt = 0; nt < 2; nt++) {
            int col = n0 + n_base + nt * 8 + 2 * (lane & 3);
            if (s_lo >= 0) {
                __half2* hp = (__half2*)(g_hh + (size_t)s_lo * HIDDEN + col);
                float a0 = acc1[mt][nt][0], a1 = acc1[mt][nt][1];
                *hp = __floats2half2_rn(a0 / (1.f + __expf(-a0)) * acc3[mt][nt][0],
                                        a1 / (1.f + __expf(-a1)) * acc3[mt][nt][1]);
            }
            if (s_hi >= 0) {
                __half2* hp = (__half2*)(g_hh + (size_t)s_hi * HIDDEN + col);
                float a2 = acc1[mt][nt][2], a3 = acc1[mt][nt][3];
                *hp = __floats2half2_rn(a2 / (1.f + __expf(-a2)) * acc3[mt][nt][2],
                                        a3 / (1.f + __expf(-a3)) * acc3[mt][nt][3]);
            }
        }
    }
}

// ============================================================================
// GEMM2 (fp16): out += wt * (h @ w2). BM=128, BN=128, BK=32, 512 threads.
// ============================================================================
#define S2 18944
#define KT2 (HIDDEN / 32)

__global__ __launch_bounds__(512, 2)
void gemm2_k(float* __restrict__ out) {
    int e = blockIdx.z, Ne = g_cnt[e];
    int m0 = blockIdx.x * 128;
    if (m0 >= Ne) return;
    int n0 = blockIdx.y * 128;

    extern __shared__ __align__(128) char sm[];
    uint32_t sb = smem_u32(sm);
    __shared__ int rtok[128], rsl[128];
    __shared__ float rwt[128];

    int tid = threadIdx.x, warp = tid >> 5, lane = tid & 31;
    if (tid < 128) {
        int r = m0 + tid;
        if (r < Ne) { rtok[tid] = g_tok[e][r]; rsl[tid] = g_slotA[e][r]; rwt[tid] = g_wt[e][r]; }
        else        { rtok[tid] = -1; rsl[tid] = 0; rwt[tid] = 0.f; }
    }
    __syncthreads();

    int am = tid >> 2, aq = tid & 3;
    const __half* asrc = g_hh + (size_t)rsl[am] * HIDDEN + aq * 8;
    uint32_t adst = sb + am * 80 + aq * 16;
    int br = tid >> 4, bq = tid & 15;
    const __half* bsrc = g_w2h + (size_t)e * HIDDEN * DIM + n0 + (size_t)br * DIM + bq * 8;
    uint32_t bdst = sb + 10240 + br * 272 + bq * 16;

    auto fill = [&](int s, int k0) {
        uint32_t so = (uint32_t)s * S2;
        CPA(adst + so, asrc + k0);
        CPA(bdst + so, bsrc + (size_t)k0 * DIM);
    };

    int m_base = (warp >> 2) * 32, n_base = (warp & 3) * 32;
    int lrow = (lane & 7) + ((lane >> 3) & 1) * 8;
    uint32_t abase = sb + (m_base + lrow) * 80 + (lane >> 4) * 16;
    uint32_t bbase = sb + 10240 + lrow * 272 + (lane >> 4) * 16 + n_base * 2;

    float acc[2][4][4];
#pragma unroll
    for (int a = 0; a < 2; a++)
#pragma unroll
        for (int b = 0; b < 4; b++)
#pragma unroll
            for (int c = 0; c < 4; c++) acc[a][b][c] = 0.f;

    fill(0, 0);  CPC();
    fill(1, 32); CPC();
    CPW1(); __syncthreads();

    int s = 0, fs = 2;
    for (int kt = 0; kt < KT2; kt++) {
        uint32_t so = (uint32_t)s * S2;
#pragma unroll
        for (int ks = 0; ks < 2; ks++) {
            unsigned a[2][4];
            ldsm4(a[0], abase + so + ks * 32);
            ldsm4(a[1], abase + so + 1280 + ks * 32);
            unsigned bf[2][4];
            uint32_t bb = bbase + so + ks * 4352;
            ldsm4t(bf[0], bb);
            ldsm4t(bf[1], bb + 32);
#pragma unroll
            for (int mt = 0; mt < 2; mt++) {
#pragma unroll
                for (int h = 0; h < 2; h++) {
                    mma16(acc[mt][h * 2 + 0], a[mt], bf[h][0], bf[h][1]);
                    mma16(acc[mt][h * 2 + 1], a[mt], bf[h][2], bf[h][3]);
                }
            }
        }
        int nk = kt + 2;
        if (nk < KT2) fill(fs, nk * 32);
        CPC();
        CPW1(); __syncthreads();
        s = (s == 2) ? 0 : s + 1;
        fs = (fs == 2) ? 0 : fs + 1;
    }
    CPW0();

#pragma unroll
    for (int mt = 0; mt < 2; mt++) {
        int mloc = m_base + mt * 16 + (lane >> 2);
        int t_lo = rtok[mloc], t_hi = rtok[mloc + 8];
        float w_lo = rwt[mloc], w_hi = rwt[mloc + 8];
#pragma unroll
        for (int nt = 0; nt < 4; nt++) {
            int col = n0 + n_base + nt * 8 + 2 * (lane & 3);
            if (t_lo >= 0) {
                atomicAdd(&out[(size_t)t_lo * DIM + col],     w_lo * acc[mt][nt][0]);
                atomicAdd(&out[(size_t)t_lo * DIM + col + 1], w_lo * acc[mt][nt][1]);
            }
            if (t_hi >= 0) {
                atomicAdd(&out[(size_t)t_hi * DIM + col],     w_hi * acc[mt][nt][2]);
                atomicAdd(&out[(size_t)t_hi * DIM + col + 1], w_hi * acc[mt][nt][3]);
            }
        }
    }
}

// ---------------- launch ----------------
extern "C" void kernel_launch(void* const* d_in, const int* in_sizes, int n_in,
                              void* d_out, int out_size) {
    const float* x  = (const float*)d_in[0];
    const float* Wg = (const float*)d_in[1];
    const float* w1 = (const float*)d_in[2];
    const float* w3 = (const float*)d_in[3];
    const float* w2 = (const float*)d_in[4];
    float* out = (float*)d_out;

    cudaFuncSetAttribute(gemm1_k, cudaFuncAttributeMaxDynamicSharedMemorySize, 3 * S1);
    cudaFuncSetAttribute(gemm2_k, cudaFuncAttributeMaxDynamicSharedMemorySize, 3 * S2);

    zero_kernel<<<1024, 256>>>(out, out_size);
    cvt_w_kernel<<<dim3(2048, 2), 256>>>(w1, w3);   // w1/w3 only; w2 rides gemm1
    cvt_x_kernel<<<512, 256>>>(x);
    gate_kernel<<<NTOK / 8, 256>>>(x, Wg);

    dim3 g1(NTOK / 128, HIDDEN / 64, NE_);          // (16, 112, 8)
    gemm1_k<<<g1, 512, 3 * S1>>>(w2);

    dim3 g2(NTOK / 128, DIM / 128, NE_);            // (16, 16, 8)
    gemm2_k<<<g2, 512, 3 * S2>>>(out);
}